// round 5
// baseline (speedup 1.0000x reference)
#include <cuda_runtime.h>
#include <cstdint>

typedef unsigned long long u64;

#define T_LEN 1024
#define NB    64
#define IDIM  128
#define HID   256
#define GDIM  1024
#define CLS   8

// scratch (device globals: allocation-free)
__device__ float g_pre[(size_t)T_LEN * NB * GDIM];   // [t][b][g]  256 MB
__device__ float g_WihT[IDIM * GDIM];                // [i][g]
__device__ float g_bsum[GDIM];

// ---------------- packed f32x2 helpers ----------------
__device__ __forceinline__ u64 pk2(float lo, float hi) {
    u64 r;
    asm("mov.b64 %0, {%1, %2};" : "=l"(r) : "r"(__float_as_uint(lo)), "r"(__float_as_uint(hi)));
    return r;
}
__device__ __forceinline__ u64 dup2(float x) {
    u64 r;
    asm("mov.b64 %0, {%1, %1};" : "=l"(r) : "r"(__float_as_uint(x)));
    return r;
}
__device__ __forceinline__ void upk2(u64 v, float& lo, float& hi) {
    uint32_t a, b;
    asm("mov.b64 {%0, %1}, %2;" : "=r"(a), "=r"(b) : "l"(v));
    lo = __uint_as_float(a); hi = __uint_as_float(b);
}
__device__ __forceinline__ u64 ffma2(u64 a, u64 b, u64 c) {
    u64 d;
    asm("fma.rn.f32x2 %0, %1, %2, %3;" : "=l"(d) : "l"(a), "l"(b), "l"(c));
    return d;
}
__device__ __forceinline__ float fsig(float x) {
    return __fdividef(1.0f, 1.0f + __expf(-x));
}
__device__ __forceinline__ float ftanh(float x) {
    return 1.0f - __fdividef(2.0f, 1.0f + __expf(2.0f * x));
}
__device__ __forceinline__ uint32_t smem_u32(const void* p) {
    return (uint32_t)__cvta_generic_to_shared(p);
}
__device__ __forceinline__ void mbar_init(uint32_t a, uint32_t cnt) {
    asm volatile("mbarrier.init.shared.b64 [%0], %1;" :: "r"(a), "r"(cnt) : "memory");
}
// wait with cluster-scope acquire (pairs with remote release-arrive)
__device__ __forceinline__ void mbar_wait(uint32_t a, uint32_t parity) {
    uint32_t done;
    asm volatile("{\n\t.reg .pred p;\n\t"
        "mbarrier.try_wait.parity.acquire.cluster.shared::cta.b64 p, [%1], %2;\n\t"
        "selp.b32 %0, 1, 0, p;\n\t}"
        : "=r"(done) : "r"(a), "r"(parity) : "memory");
    if (!done) {
        asm volatile("{\n\t.reg .pred P1;\n\t"
            "W_%=:\n\t"
            "mbarrier.try_wait.parity.acquire.cluster.shared::cta.b64 P1, [%0], %1, 0x989680;\n\t"
            "@P1 bra.uni D_%=;\n\t"
            "bra.uni W_%=;\n\t"
            "D_%=:\n\t}"
            :: "r"(a), "r"(parity) : "memory");
    }
}
__device__ __forceinline__ void st_remote_v4(uint32_t raddr, float a, float b, float c, float d) {
    asm volatile("st.shared::cluster.v4.f32 [%0], {%1, %2, %3, %4};"
                 :: "r"(raddr), "f"(a), "f"(b), "f"(c), "f"(d) : "memory");
}
__device__ __forceinline__ void mbar_arrive_remote(uint32_t raddr) {
    asm volatile("mbarrier.arrive.release.cluster.shared::cluster.b64 _, [%0];"
                 :: "r"(raddr) : "memory");
}

// =====================================================================
// Kernel 0: transpose W_ih -> g_WihT[i][g]; bias sum
// =====================================================================
__global__ void prep_kernel(const float* __restrict__ W_ih,
                            const float* __restrict__ b_ih,
                            const float* __restrict__ b_hh) {
    int idx = blockIdx.x * 256 + threadIdx.x;
    int i = idx >> 10;
    int g = idx & 1023;
    g_WihT[idx] = W_ih[g * IDIM + i];
    if (idx < GDIM) g_bsum[idx] = b_ih[idx] + b_hh[idx];
}

// dummy kernel to shift ncu's -s window onto lstm_rec
__global__ void nudge_kernel() {}

// =====================================================================
// Kernel 1: pre[t][b][g] = sum_i x[b][i][t] * W_ih[g][i] + bsum[g]
// =====================================================================
#define XS_STRIDE 68
#define WS_STRIDE 132
#define SMEM1 ((IDIM * XS_STRIDE + IDIM * WS_STRIDE) * 4)

__global__ __launch_bounds__(256, 2) void gemm_pre(const float* __restrict__ x) {
    extern __shared__ float sm[];
    float* x_s = sm;
    float* w_s = sm + IDIM * XS_STRIDE;

    int tid = threadIdx.x;
    int g0 = blockIdx.x * 128;
    int t0 = blockIdx.y * 64;
    int b  = blockIdx.z;

    const float* xb = x + (size_t)b * IDIM * T_LEN;
    #pragma unroll
    for (int idx = tid; idx < 128 * 16; idx += 256) {
        int i = idx >> 4, c4 = idx & 15;
        float4 v = *(const float4*)(xb + (size_t)i * T_LEN + t0 + 4 * c4);
        *(float4*)(x_s + i * XS_STRIDE + 4 * c4) = v;
    }
    #pragma unroll
    for (int idx = tid; idx < 128 * 32; idx += 256) {
        int i = idx >> 5, c4 = idx & 31;
        float4 v = *(const float4*)(g_WihT + (size_t)i * GDIM + g0 + 4 * c4);
        *(float4*)(w_s + i * WS_STRIDE + 4 * c4) = v;
    }
    __syncthreads();

    int tx = tid & 15;
    int ty = tid >> 4;

    u64 acc[4][4];
    #pragma unroll
    for (int a = 0; a < 4; a++)
        #pragma unroll
        for (int c = 0; c < 4; c++) acc[a][c] = 0ull;

    const float* xp = x_s + 4 * ty;
    const float* wp = w_s + 8 * tx;

    #pragma unroll 4
    for (int k = 0; k < 128; k++) {
        float4 xv = *(const float4*)(xp + k * XS_STRIDE);
        ulonglong2 wa = *(const ulonglong2*)(wp + k * WS_STRIDE);
        ulonglong2 wb = *(const ulonglong2*)(wp + k * WS_STRIDE + 4);
        u64 d0 = dup2(xv.x), d1 = dup2(xv.y), d2 = dup2(xv.z), d3 = dup2(xv.w);
        acc[0][0] = ffma2(d0, wa.x, acc[0][0]);
        acc[0][1] = ffma2(d0, wa.y, acc[0][1]);
        acc[0][2] = ffma2(d0, wb.x, acc[0][2]);
        acc[0][3] = ffma2(d0, wb.y, acc[0][3]);
        acc[1][0] = ffma2(d1, wa.x, acc[1][0]);
        acc[1][1] = ffma2(d1, wa.y, acc[1][1]);
        acc[1][2] = ffma2(d1, wb.x, acc[1][2]);
        acc[1][3] = ffma2(d1, wb.y, acc[1][3]);
        acc[2][0] = ffma2(d2, wa.x, acc[2][0]);
        acc[2][1] = ffma2(d2, wa.y, acc[2][1]);
        acc[2][2] = ffma2(d2, wb.x, acc[2][2]);
        acc[2][3] = ffma2(d2, wb.y, acc[2][3]);
        acc[3][0] = ffma2(d3, wa.x, acc[3][0]);
        acc[3][1] = ffma2(d3, wa.y, acc[3][1]);
        acc[3][2] = ffma2(d3, wb.x, acc[3][2]);
        acc[3][3] = ffma2(d3, wb.y, acc[3][3]);
    }

    float4 bsa = *(const float4*)(g_bsum + g0 + 8 * tx);
    float4 bsb = *(const float4*)(g_bsum + g0 + 8 * tx + 4);

    #pragma unroll
    for (int tt = 0; tt < 4; tt++) {
        float l0, h0, l1, h1, l2, h2, l3, h3;
        upk2(acc[tt][0], l0, h0);
        upk2(acc[tt][1], l1, h1);
        upk2(acc[tt][2], l2, h2);
        upk2(acc[tt][3], l3, h3);
        float4 o1 = make_float4(l0 + bsa.x, h0 + bsa.y, l1 + bsa.z, h1 + bsa.w);
        float4 o2 = make_float4(l2 + bsb.x, h2 + bsb.y, l3 + bsb.z, h3 + bsb.w);
        size_t base = ((size_t)(t0 + 4 * ty + tt) * NB + b) * GDIM + g0 + 8 * tx;
        *(float4*)(g_pre + base)     = o1;
        *(float4*)(g_pre + base + 4) = o2;
    }
}

// =====================================================================
// Kernel 2: recurrence, bulk-store + count-arrive protocol.
// 16 clusters x 8 CTAs, 512 threads. cluster owns 4 batches; rank owns 32 u.
// matmul: warp w: kq=w>>1 (32-k slice), half=w&1; lane owns 2 rows.
// act (tid<128): u = tid&31 (lane), bl = tid>>5 (warp). leaders (lane%4==0)
// gather 4 h via shfl, push v4 to all ranks' h_buf[nxt]; named-bar; 8 threads
// do one release-arrive each on the peers' bar[nxt] (count=8, auto-reset).
// =====================================================================
__global__ __launch_bounds__(512, 1) __cluster_dims__(CLS, 1, 1)
void lstm_rec(const float* __restrict__ W_hh, float* __restrict__ out) {
    __shared__ float h_buf[2][4][HID];       // [buf][b][u] 8KB (offset 0)
    __shared__ float red[2][32 * 133];       // ping-pong partials
    __shared__ float pre_s[16 * 33];
    __shared__ u64  mbar[2];

    int tid  = threadIdx.x;
    int rank = blockIdx.x & (CLS - 1);
    int cid  = blockIdx.x >> 3;
    int w    = tid >> 5, lane = tid & 31;
    int kq   = w >> 1, half = w & 1;

    uint32_t hbase_loc = smem_u32(&h_buf[0][0][0]);
    uint32_t bar_loc   = smem_u32(&mbar[0]);

    // ---- W_hh slice -> registers
    u64 wreg[2][8][2];
    #pragma unroll
    for (int rr = 0; rr < 2; rr++) {
        int gate = 2 * half + rr;
        int grow = (gate << 8) + (rank << 5) + lane;
        const float* wr = W_hh + (size_t)grow * HID + (kq << 5);
        #pragma unroll
        for (int j = 0; j < 8; j++) {
            float4 v = *(const float4*)(wr + 4 * j);
            wreg[rr][j][0] = pk2(v.x, v.y);
            wreg[rr][j][1] = pk2(v.z, v.w);
        }
    }

    for (int i = tid; i < 2 * 4 * HID; i += 512) ((float*)h_buf)[i] = 0.0f;
    if (tid == 0) {
        mbar_init(bar_loc, CLS);       // bar[0]
        mbar_init(bar_loc + 8, CLS);   // bar[1]
    }
    __syncthreads();
    asm volatile("barrier.cluster.arrive.aligned;\n\tbarrier.cluster.wait.aligned;" ::: "memory");

    // remote smem bases per rank (mapa affine)
    uint32_t rbase[CLS];
    #pragma unroll
    for (int r = 0; r < CLS; r++)
        asm volatile("mapa.shared::cluster.u32 %0, %1, %2;" : "=r"(rbase[r]) : "r"(hbase_loc), "r"(r));
    uint32_t bar_off = bar_loc - hbase_loc;

    // activation role (tid < 128): u = lane, bl = warp
    int u  = lane;
    int bl = tid >> 5;
    float c_st = 0.0f;
    float o0 = 0.f, o1 = 0.f, o2 = 0.f, o3 = 0.f;
    size_t out_base = ((size_t)(4 * cid + bl) * HID + (rank << 5) + u) * T_LEN;
    // leader's v4 slot within a buf: (bl*256 + rank*32 + (u&~3)) * 4 bytes
    uint32_t v4_off = (uint32_t)((((bl << 8) + (rank << 5) + (u & ~3)) << 2));

    // pre prefetch role
    int pc = tid >> 5, plane = tid & 31;
    int pgate = pc >> 2, pb = pc & 3;
    size_t pre_base = (size_t)(4 * cid + pb) * GDIM + (pgate << 8) + (rank << 5) + plane;

    uint32_t parity0 = 0, parity1 = 0;

    for (int t = 0; t < T_LEN; t++) {
        int cur = t & 1, nxt = cur ^ 1;

        float prev = __ldg(g_pre + (size_t)t * (NB * GDIM) + pre_base);

        if (t > 0) {
            if (cur) { mbar_wait(bar_loc + 8, parity1); parity1 ^= 1; }
            else     { mbar_wait(bar_loc,     parity0); parity0 ^= 1; }
        }

        // ---- matmul partials: 2 rows x 4 batches, 32-k slice (broadcast h)
        float pr[2][4];
        const float* hb = &h_buf[cur][0][0];
        #pragma unroll
        for (int b = 0; b < 4; b++) {
            u64 a0 = 0ull, a1 = 0ull;
            const ulonglong2* hp = (const ulonglong2*)(hb + (b << 8) + (kq << 5));
            #pragma unroll
            for (int j = 0; j < 8; j++) {
                ulonglong2 hv = hp[j];
                a0 = ffma2(hv.x, wreg[0][j][0], a0);
                a0 = ffma2(hv.y, wreg[0][j][1], a0);
                a1 = ffma2(hv.x, wreg[1][j][0], a1);
                a1 = ffma2(hv.y, wreg[1][j][1], a1);
            }
            float lo, hi;
            upk2(a0, lo, hi); pr[0][b] = lo + hi;
            upk2(a1, lo, hi); pr[1][b] = lo + hi;
        }

        // ---- scatter partials (ping-pong buffer)
        float* rd = red[cur];
        #pragma unroll
        for (int rr = 0; rr < 2; rr++) {
            int l = ((2 * half + rr) << 5) + lane;
            #pragma unroll
            for (int b = 0; b < 4; b++)
                rd[(b * 8 + kq) * 133 + l] = pr[rr][b];
        }
        pre_s[pc * 33 + plane] = prev;
        __syncthreads();

        if (tid < 128) {
            float g4[4];
            #pragma unroll
            for (int gate = 0; gate < 4; gate++) {
                int l = (gate << 5) + u;
                float s = pre_s[(gate * 4 + bl) * 33 + u];
                #pragma unroll
                for (int k = 0; k < 8; k++)
                    s += rd[(bl * 8 + k) * 133 + l];
                g4[gate] = s;
            }
            float ig = fsig(g4[0]), fg = fsig(g4[1]);
            float gg = ftanh(g4[2]), og = fsig(g4[3]);
            c_st = fg * c_st + ig * gg;
            float h = og * ftanh(c_st);
            float hr = fmaxf(h, 0.0f);

            int ph = t & 3;
            if (ph == 0) o0 = hr; else if (ph == 1) o1 = hr;
            else if (ph == 2) o2 = hr; else o3 = hr;
            if (ph == 3)
                *(float4*)(out + out_base + (t - 3)) = make_float4(o0, o1, o2, o3);

            // gather 4 consecutive-u h values into leaders, bulk-push v4
            float h1v = __shfl_down_sync(0xffffffffu, h, 1);
            float h2v = __shfl_down_sync(0xffffffffu, h, 2);
            float h3v = __shfl_down_sync(0xffffffffu, h, 3);
            if ((u & 3) == 0) {
                uint32_t hoff = (uint32_t)(nxt * 4096) + v4_off;
                #pragma unroll
                for (int r = 0; r < CLS; r++)
                    st_remote_v4(rbase[r] + hoff, h, h1v, h2v, h3v);
            }
            // order all act-thread stores, then 8 release-arrives (one per rank)
            asm volatile("bar.sync 1, 128;" ::: "memory");
            if (tid < CLS)
                mbar_arrive_remote(rbase[tid] + bar_off + 8u * (uint32_t)nxt);
        }
    }
    asm volatile("barrier.cluster.arrive.aligned;\n\tbarrier.cluster.wait.aligned;" ::: "memory");
}

// =====================================================================
extern "C" void kernel_launch(void* const* d_in, const int* in_sizes, int n_in,
                              void* d_out, int out_size) {
    const float* x    = (const float*)d_in[0];
    const float* W_ih = (const float*)d_in[1];
    const float* W_hh = (const float*)d_in[2];
    const float* b_ih = (const float*)d_in[3];
    const float* b_hh = (const float*)d_in[4];
    float* out = (float*)d_out;

    prep_kernel<<<512, 256>>>(W_ih, b_ih, b_hh);

    cudaFuncSetAttribute(gemm_pre, cudaFuncAttributeMaxDynamicSharedMemorySize, SMEM1);
    dim3 grid1(GDIM / 128, T_LEN / 64, NB);
    gemm_pre<<<grid1, 256, SMEM1>>>(x);

    // shift ncu's skip window so the capture lands on lstm_rec
    nudge_kernel<<<1, 32>>>();
    nudge_kernel<<<1, 32>>>();
    nudge_kernel<<<1, 32>>>();

    lstm_rec<<<NB / 4 * CLS, 512>>>(W_hh, out);
}

// round 6
// speedup vs baseline: 1.2493x; 1.2493x over previous
#include <cuda_runtime.h>
#include <cstdint>

typedef unsigned long long u64;

#define T_LEN 1024
#define NB    64
#define IDIM  128
#define HID   256
#define GDIM  1024
#define CLS   8

// scratch (device globals: allocation-free)
__device__ float g_pre[(size_t)T_LEN * NB * GDIM];   // [t][b][g]  256 MB
__device__ float g_WihT[IDIM * GDIM];                // [i][g]
__device__ float g_bsum[GDIM];

// ---------------- packed f32x2 helpers ----------------
__device__ __forceinline__ u64 pk2(float lo, float hi) {
    u64 r;
    asm("mov.b64 %0, {%1, %2};" : "=l"(r) : "r"(__float_as_uint(lo)), "r"(__float_as_uint(hi)));
    return r;
}
__device__ __forceinline__ u64 dup2(float x) {
    u64 r;
    asm("mov.b64 %0, {%1, %1};" : "=l"(r) : "r"(__float_as_uint(x)));
    return r;
}
__device__ __forceinline__ void upk2(u64 v, float& lo, float& hi) {
    uint32_t a, b;
    asm("mov.b64 {%0, %1}, %2;" : "=r"(a), "=r"(b) : "l"(v));
    lo = __uint_as_float(a); hi = __uint_as_float(b);
}
__device__ __forceinline__ u64 ffma2(u64 a, u64 b, u64 c) {
    u64 d;
    asm("fma.rn.f32x2 %0, %1, %2, %3;" : "=l"(d) : "l"(a), "l"(b), "l"(c));
    return d;
}
__device__ __forceinline__ float fsig(float x) {
    return __fdividef(1.0f, 1.0f + __expf(-x));
}
__device__ __forceinline__ float ftanh(float x) {
    return 1.0f - __fdividef(2.0f, 1.0f + __expf(2.0f * x));
}
__device__ __forceinline__ uint32_t smem_u32(const void* p) {
    return (uint32_t)__cvta_generic_to_shared(p);
}
__device__ __forceinline__ void mbar_init(uint32_t a, uint32_t cnt) {
    asm volatile("mbarrier.init.shared.b64 [%0], %1;" :: "r"(a), "r"(cnt) : "memory");
}
__device__ __forceinline__ void mbar_arrive_expect(uint32_t a, uint32_t tx) {
    asm volatile("mbarrier.arrive.expect_tx.shared.b64 _, [%0], %1;" :: "r"(a), "r"(tx) : "memory");
}
__device__ __forceinline__ void mbar_wait(uint32_t a, uint32_t parity) {
    uint32_t done;
    asm volatile("{\n\t.reg .pred p;\n\t"
        "mbarrier.try_wait.parity.acquire.cta.shared::cta.b64 p, [%1], %2;\n\t"
        "selp.b32 %0, 1, 0, p;\n\t}"
        : "=r"(done) : "r"(a), "r"(parity) : "memory");
    if (!done) {
        asm volatile("{\n\t.reg .pred P1;\n\t"
            "W_%=:\n\t"
            "mbarrier.try_wait.parity.acquire.cta.shared::cta.b64 P1, [%0], %1, 0x989680;\n\t"
            "@P1 bra.uni D_%=;\n\t"
            "bra.uni W_%=;\n\t"
            "D_%=:\n\t}"
            :: "r"(a), "r"(parity) : "memory");
    }
}
__device__ __forceinline__ void st_async_b64(uint32_t raddr, u64 v, uint32_t rbar) {
    asm volatile("st.async.shared::cluster.mbarrier::complete_tx::bytes.b64 [%0], %1, [%2];"
                 :: "r"(raddr), "l"(v), "r"(rbar) : "memory");
}

// =====================================================================
// Kernel 0: transpose W_ih -> g_WihT[i][g]; bias sum
// =====================================================================
__global__ void prep_kernel(const float* __restrict__ W_ih,
                            const float* __restrict__ b_ih,
                            const float* __restrict__ b_hh) {
    int idx = blockIdx.x * 256 + threadIdx.x;
    int i = idx >> 10;
    int g = idx & 1023;
    g_WihT[idx] = W_ih[g * IDIM + i];
    if (idx < GDIM) g_bsum[idx] = b_ih[idx] + b_hh[idx];
}

// dummy kernel so lstm_rec is the 4th launch (ncu captures launch #4)
__global__ void nudge_kernel() {}

// =====================================================================
// Kernel 1: pre[t][b][g] = sum_i x[b][i][t] * W_ih[g][i] + bsum[g]
// =====================================================================
#define XS_STRIDE 68
#define WS_STRIDE 132
#define SMEM1 ((IDIM * XS_STRIDE + IDIM * WS_STRIDE) * 4)

__global__ __launch_bounds__(256, 2) void gemm_pre(const float* __restrict__ x) {
    extern __shared__ float sm[];
    float* x_s = sm;
    float* w_s = sm + IDIM * XS_STRIDE;

    int tid = threadIdx.x;
    int g0 = blockIdx.x * 128;
    int t0 = blockIdx.y * 64;
    int b  = blockIdx.z;

    const float* xb = x + (size_t)b * IDIM * T_LEN;
    #pragma unroll
    for (int idx = tid; idx < 128 * 16; idx += 256) {
        int i = idx >> 4, c4 = idx & 15;
        float4 v = *(const float4*)(xb + (size_t)i * T_LEN + t0 + 4 * c4);
        *(float4*)(x_s + i * XS_STRIDE + 4 * c4) = v;
    }
    #pragma unroll
    for (int idx = tid; idx < 128 * 32; idx += 256) {
        int i = idx >> 5, c4 = idx & 31;
        float4 v = *(const float4*)(g_WihT + (size_t)i * GDIM + g0 + 4 * c4);
        *(float4*)(w_s + i * WS_STRIDE + 4 * c4) = v;
    }
    __syncthreads();

    int tx = tid & 15;
    int ty = tid >> 4;

    u64 acc[4][4];
    #pragma unroll
    for (int a = 0; a < 4; a++)
        #pragma unroll
        for (int c = 0; c < 4; c++) acc[a][c] = 0ull;

    const float* xp = x_s + 4 * ty;
    const float* wp = w_s + 8 * tx;

    #pragma unroll 4
    for (int k = 0; k < 128; k++) {
        float4 xv = *(const float4*)(xp + k * XS_STRIDE);
        ulonglong2 wa = *(const ulonglong2*)(wp + k * WS_STRIDE);
        ulonglong2 wb = *(const ulonglong2*)(wp + k * WS_STRIDE + 4);
        u64 d0 = dup2(xv.x), d1 = dup2(xv.y), d2 = dup2(xv.z), d3 = dup2(xv.w);
        acc[0][0] = ffma2(d0, wa.x, acc[0][0]);
        acc[0][1] = ffma2(d0, wa.y, acc[0][1]);
        acc[0][2] = ffma2(d0, wb.x, acc[0][2]);
        acc[0][3] = ffma2(d0, wb.y, acc[0][3]);
        acc[1][0] = ffma2(d1, wa.x, acc[1][0]);
        acc[1][1] = ffma2(d1, wa.y, acc[1][1]);
        acc[1][2] = ffma2(d1, wb.x, acc[1][2]);
        acc[1][3] = ffma2(d1, wb.y, acc[1][3]);
        acc[2][0] = ffma2(d2, wa.x, acc[2][0]);
        acc[2][1] = ffma2(d2, wa.y, acc[2][1]);
        acc[2][2] = ffma2(d2, wb.x, acc[2][2]);
        acc[2][3] = ffma2(d2, wb.y, acc[2][3]);
        acc[3][0] = ffma2(d3, wa.x, acc[3][0]);
        acc[3][1] = ffma2(d3, wa.y, acc[3][1]);
        acc[3][2] = ffma2(d3, wb.x, acc[3][2]);
        acc[3][3] = ffma2(d3, wb.y, acc[3][3]);
    }

    float4 bsa = *(const float4*)(g_bsum + g0 + 8 * tx);
    float4 bsb = *(const float4*)(g_bsum + g0 + 8 * tx + 4);

    #pragma unroll
    for (int tt = 0; tt < 4; tt++) {
        float l0, h0, l1, h1, l2, h2, l3, h3;
        upk2(acc[tt][0], l0, h0);
        upk2(acc[tt][1], l1, h1);
        upk2(acc[tt][2], l2, h2);
        upk2(acc[tt][3], l3, h3);
        float4 o1 = make_float4(l0 + bsa.x, h0 + bsa.y, l1 + bsa.z, h1 + bsa.w);
        float4 o2 = make_float4(l2 + bsb.x, h2 + bsb.y, l3 + bsb.z, h3 + bsb.w);
        size_t base = ((size_t)(t0 + 4 * ty + tt) * NB + b) * GDIM + g0 + 8 * tx;
        *(float4*)(g_pre + base)     = o1;
        *(float4*)(g_pre + base + 4) = o2;
    }
}

// =====================================================================
// Kernel 2: recurrence (R4 st.async protocol, b64-packed pushes).
// 16 clusters x 8 CTAs, 512 threads. cluster owns 4 batches; rank owns 32 u.
// matmul: warp w: kq=w>>1 (32-k slice), half=w&1; lane owns 2 rows; h reads
// are warp-uniform broadcasts. act (tid<128): u=tid>>2, bl=tid&3.
// Even-u act threads push (h[u],h[u+1]) as one st.async.b64 per rank:
// 512 tx per receiving barrier per step (was 1024).
// =====================================================================
__global__ __launch_bounds__(512, 1) __cluster_dims__(CLS, 1, 1)
void lstm_rec(const float* __restrict__ W_hh, float* __restrict__ out) {
    __shared__ float h_buf[2][4][HID];       // [buf][b][u] 8KB (offset 0)
    __shared__ float red[2][32 * 133];       // ping-pong partials
    __shared__ float pre_s[16 * 36];
    __shared__ u64  mbar[2];

    int tid  = threadIdx.x;
    int rank = blockIdx.x & (CLS - 1);
    int cid  = blockIdx.x >> 3;
    int w    = tid >> 5, lane = tid & 31;
    int kq   = w >> 1, half = w & 1;

    uint32_t hbase_loc = smem_u32(&h_buf[0][0][0]);
    uint32_t bar_loc   = smem_u32(&mbar[0]);

    // ---- W_hh slice -> registers
    u64 wreg[2][8][2];
    #pragma unroll
    for (int rr = 0; rr < 2; rr++) {
        int gate = 2 * half + rr;
        int grow = (gate << 8) + (rank << 5) + lane;
        const float* wr = W_hh + (size_t)grow * HID + (kq << 5);
        #pragma unroll
        for (int j = 0; j < 8; j++) {
            float4 v = *(const float4*)(wr + 4 * j);
            wreg[rr][j][0] = pk2(v.x, v.y);
            wreg[rr][j][1] = pk2(v.z, v.w);
        }
    }

    for (int i = tid; i < 2 * 4 * HID; i += 512) ((float*)h_buf)[i] = 0.0f;
    if (tid == 0) {
        mbar_init(bar_loc, 1);
        mbar_init(bar_loc + 8, 1);
        mbar_arrive_expect(bar_loc, 4096);      // armed for step-2 wait
        mbar_arrive_expect(bar_loc + 8, 4096);  // armed for step-1 wait
    }
    __syncthreads();
    asm volatile("barrier.cluster.arrive.aligned;\n\tbarrier.cluster.wait.aligned;" ::: "memory");

    // remote smem bases per rank (mapa affine)
    uint32_t rbase[CLS];
    #pragma unroll
    for (int r = 0; r < CLS; r++)
        asm volatile("mapa.shared::cluster.u32 %0, %1, %2;" : "=r"(rbase[r]) : "r"(hbase_loc), "r"(r));
    uint32_t bar_off = bar_loc - hbase_loc;

    // activation role (tid < 128)
    int u  = tid >> 2;
    int bl = tid & 3;
    float c_st = 0.0f;
    float o0 = 0.f, o1 = 0.f, o2 = 0.f, o3 = 0.f;
    size_t out_base = ((size_t)(4 * cid + bl) * HID + (rank << 5) + u) * T_LEN;
    // b64 slot (covers u, u+1) within a buf, for even u
    uint32_t pair_off = (uint32_t)(((bl << 8) + (rank << 5) + (u & ~1)) << 2);

    // pre prefetch role
    int pc = tid >> 5, plane = tid & 31;
    int pgate = pc >> 2, pb = pc & 3;
    size_t pre_base = (size_t)(4 * cid + pb) * GDIM + (pgate << 8) + (rank << 5) + plane;

    uint32_t parity0 = 0, parity1 = 0;

    for (int t = 0; t < T_LEN; t++) {
        int cur = t & 1, nxt = cur ^ 1;

        float prev = __ldg(g_pre + (size_t)t * (NB * GDIM) + pre_base);

        if (t > 0) {
            if (cur) { mbar_wait(bar_loc + 8, parity1); parity1 ^= 1; }
            else     { mbar_wait(bar_loc,     parity0); parity0 ^= 1; }
            if (tid == 0)  // re-arm for step t+2
                mbar_arrive_expect(bar_loc + 8 * (uint32_t)cur, 4096);
        }

        // ---- matmul partials: 2 rows x 4 batches, 32-k slice (broadcast h)
        float pr[2][4];
        const float* hb = &h_buf[cur][0][0];
        #pragma unroll
        for (int b = 0; b < 4; b++) {
            u64 a0 = 0ull, a1 = 0ull;
            const ulonglong2* hp = (const ulonglong2*)(hb + (b << 8) + (kq << 5));
            #pragma unroll
            for (int j = 0; j < 8; j++) {
                ulonglong2 hv = hp[j];
                a0 = ffma2(hv.x, wreg[0][j][0], a0);
                a0 = ffma2(hv.y, wreg[0][j][1], a0);
                a1 = ffma2(hv.x, wreg[1][j][0], a1);
                a1 = ffma2(hv.y, wreg[1][j][1], a1);
            }
            float lo, hi;
            upk2(a0, lo, hi); pr[0][b] = lo + hi;
            upk2(a1, lo, hi); pr[1][b] = lo + hi;
        }

        // ---- scatter partials (ping-pong buffer)
        float* rd = red[cur];
        #pragma unroll
        for (int rr = 0; rr < 2; rr++) {
            int l = ((2 * half + rr) << 5) + lane;
            #pragma unroll
            for (int b = 0; b < 4; b++)
                rd[(b * 8 + kq) * 133 + l] = pr[rr][b];
        }
        pre_s[pc * 36 + plane] = prev;
        __syncthreads();

        if (tid < 128) {
            float g4[4];
            #pragma unroll
            for (int gate = 0; gate < 4; gate++) {
                int l = (gate << 5) + u;
                const float* rp = rd + l;
                float s0 = rd[(bl * 8 + 0) * 133 + l] + rd[(bl * 8 + 1) * 133 + l];
                float s1 = rd[(bl * 8 + 2) * 133 + l] + rd[(bl * 8 + 3) * 133 + l];
                float s2 = rd[(bl * 8 + 4) * 133 + l] + rd[(bl * 8 + 5) * 133 + l];
                float s3 = rd[(bl * 8 + 6) * 133 + l] + rd[(bl * 8 + 7) * 133 + l];
                g4[gate] = ((s0 + s1) + (s2 + s3)) + pre_s[(gate * 4 + bl) * 36 + u];
            }
            float ig = fsig(g4[0]), fg = fsig(g4[1]);
            float gg = ftanh(g4[2]), og = fsig(g4[3]);
            c_st = fg * c_st + ig * gg;
            float h = og * ftanh(c_st);

            // push h pair FIRST (critical path), bookkeeping after
            float h_up = __shfl_down_sync(0xffffffffu, h, 4);  // h of u+1, same bl
            if ((u & 1) == 0) {
                u64 hv2 = pk2(h, h_up);
                uint32_t hoff = (uint32_t)(nxt * 4096) + pair_off;
                uint32_t boff = bar_off + 8u * (uint32_t)nxt;
                #pragma unroll
                for (int r = 0; r < CLS; r++)
                    st_async_b64(rbase[r] + hoff, hv2, rbase[r] + boff);
            }

            float hr = fmaxf(h, 0.0f);
            int ph = t & 3;
            if (ph == 0) o0 = hr; else if (ph == 1) o1 = hr;
            else if (ph == 2) o2 = hr; else o3 = hr;
            if (ph == 3)
                *(float4*)(out + out_base + (t - 3)) = make_float4(o0, o1, o2, o3);
        }
    }
    asm volatile("barrier.cluster.arrive.aligned;\n\tbarrier.cluster.wait.aligned;" ::: "memory");
}

// =====================================================================
extern "C" void kernel_launch(void* const* d_in, const int* in_sizes, int n_in,
                              void* d_out, int out_size) {
    const float* x    = (const float*)d_in[0];
    const float* W_ih = (const float*)d_in[1];
    const float* W_hh = (const float*)d_in[2];
    const float* b_ih = (const float*)d_in[3];
    const float* b_hh = (const float*)d_in[4];
    float* out = (float*)d_out;

    prep_kernel<<<512, 256>>>(W_ih, b_ih, b_hh);                 // launch 1

    cudaFuncSetAttribute(gemm_pre, cudaFuncAttributeMaxDynamicSharedMemorySize, SMEM1);
    dim3 grid1(GDIM / 128, T_LEN / 64, NB);
    gemm_pre<<<grid1, 256, SMEM1>>>(x);                          // launch 2

    nudge_kernel<<<1, 32>>>();                                   // launch 3

    lstm_rec<<<NB / 4 * CLS, 512>>>(W_hh, out);                  // launch 4 (ncu target)
}